// round 1
// baseline (speedup 1.0000x reference)
#include <cuda_runtime.h>
#include <math.h>

#define BATCH 32
#define CIN   256
#define COUT  256
#define NEXP  4
#define HH    56
#define WW    56
#define HWSZ  3136

// Scratch (allocation-free rule: __device__ globals)
__device__ float g_pooled[BATCH * CIN];
__device__ float g_att[BATCH * NEXP];
// agg[b][ci][t][o]  (o contiguous -> LDS.128 over 4 couts in conv kernel)
__device__ float g_aggw[(size_t)BATCH * CIN * 9 * COUT];

// ---------------------------------------------------------------------------
// Kernel 1: per-(b,c) spatial mean.  grid = B*CIN blocks, 256 threads.
// ---------------------------------------------------------------------------
__global__ void mean_kernel(const float* __restrict__ x) {
    int bc = blockIdx.x;
    const float4* p = reinterpret_cast<const float4*>(x + (size_t)bc * HWSZ);
    float s = 0.f;
    for (int i = threadIdx.x; i < HWSZ / 4; i += 256) {
        float4 v = p[i];
        s += (v.x + v.y) + (v.z + v.w);
    }
    #pragma unroll
    for (int o = 16; o; o >>= 1) s += __shfl_xor_sync(0xffffffffu, s, o);
    __shared__ float ws[8];
    if ((threadIdx.x & 31) == 0) ws[threadIdx.x >> 5] = s;
    __syncthreads();
    if (threadIdx.x == 0) {
        float t = 0.f;
        #pragma unroll
        for (int i = 0; i < 8; i++) t += ws[i];
        g_pooled[bc] = t * (1.0f / (float)HWSZ);
    }
}

// ---------------------------------------------------------------------------
// Kernel 2: att[b][k] = sigmoid(pooled[b] . att_w[k]).  1 block, 128 threads.
// ---------------------------------------------------------------------------
__global__ void att_kernel(const float* __restrict__ att_w) {
    int idx = threadIdx.x;           // b*4 + k
    int b = idx >> 2, k = idx & 3;
    const float* pr = g_pooled + b * CIN;
    const float* wr = att_w + k * CIN;
    float s = 0.f;
    #pragma unroll 8
    for (int c = 0; c < CIN; c++) s += pr[c] * wr[c];
    g_att[idx] = 1.0f / (1.0f + expf(-s));
}

// ---------------------------------------------------------------------------
// Kernel 3: agg[b][ci][t][o] = sum_k att[b,k] * w[k][o][ci][t]
// grid = (CIN, BATCH), 256 threads (thread = o). Coalesced writes per t.
// ---------------------------------------------------------------------------
__global__ void agg_kernel(const float* __restrict__ weight) {
    int ci = blockIdx.x;
    int b  = blockIdx.y;
    int o  = threadIdx.x;
    float acc[9];
    #pragma unroll
    for (int t = 0; t < 9; t++) acc[t] = 0.f;
    #pragma unroll
    for (int k = 0; k < NEXP; k++) {
        float a = g_att[b * NEXP + k];
        const float* wp = weight + (((size_t)(k * COUT + o)) * CIN + ci) * 9;
        #pragma unroll
        for (int t = 0; t < 9; t++) acc[t] += a * wp[t];
    }
    float* op = g_aggw + ((size_t)(b * CIN + ci)) * 9 * COUT + o;
    #pragma unroll
    for (int t = 0; t < 9; t++) op[t * COUT] = acc[t];
}

// ---------------------------------------------------------------------------
// Kernel 4: direct conv. Block tile: 64 couts x (8x8) pixels, 256 threads.
// Per-thread micro-tile: 4 couts x (2x2) pixels, 4x4 x-patch cached in regs.
// grid = (49 spatial, 4 cout-groups, 32 batch)
// ---------------------------------------------------------------------------
__global__ void __launch_bounds__(256) conv_kernel(const float* __restrict__ x,
                                                   float* __restrict__ out) {
    __shared__ float  x_s[8 * 100];      // 8 ci x 10 x 10 halo tile
    __shared__ float4 w_s[72 * 16];      // [ci*9+t][16 x float4] = 64 couts

    const int b   = blockIdx.z;
    const int o0  = blockIdx.y * 64;
    const int sp  = blockIdx.x;
    const int h0  = (sp / 7) * 8;
    const int w0  = (sp % 7) * 8;
    const int tid = threadIdx.x;
    const int pix = tid & 15;            // 4x4 grid of 2x2 pixel blocks
    const int cg  = tid >> 4;            // cout group-of-4 (0..15)
    const int pr  = (pix >> 2) * 2;
    const int pc  = (pix & 3) * 2;

    float acc[4][2][2];
    #pragma unroll
    for (int oi = 0; oi < 4; oi++)
        #pragma unroll
        for (int i = 0; i < 2; i++)
            #pragma unroll
            for (int j = 0; j < 2; j++) acc[oi][i][j] = 0.f;

    const float* xb = x + (size_t)b * CIN * HWSZ;

    for (int ci0 = 0; ci0 < CIN; ci0 += 8) {
        // --- stage x halo tile (zero-padded) ---
        for (int idx = tid; idx < 800; idx += 256) {
            int ci  = idx / 100;
            int rem = idx - ci * 100;
            int r   = rem / 10;
            int c   = rem - r * 10;
            int hh  = h0 + r - 1;
            int ww  = w0 + c - 1;
            float v = 0.f;
            if (hh >= 0 && hh < HH && ww >= 0 && ww < WW)
                v = xb[(size_t)(ci0 + ci) * HWSZ + hh * WW + ww];
            x_s[idx] = v;
        }
        // --- stage aggregated weights: 72 rows x 64 couts (1152 float4) ---
        const float4* wg = reinterpret_cast<const float4*>(
            g_aggw + ((size_t)(b * CIN + ci0)) * 9 * COUT + o0);
        for (int f = tid; f < 1152; f += 256) {
            int row = f >> 4;            // ci*9 + t
            int q   = f & 15;
            w_s[f] = wg[row * 64 + q];   // global row pitch = 256 floats = 64 float4
        }
        __syncthreads();

        #pragma unroll
        for (int ci = 0; ci < 8; ci++) {
            float xv[4][4];
            #pragma unroll
            for (int rr = 0; rr < 4; rr++)
                #pragma unroll
                for (int cc = 0; cc < 4; cc++)
                    xv[rr][cc] = x_s[ci * 100 + (pr + rr) * 10 + (pc + cc)];
            #pragma unroll
            for (int t = 0; t < 9; t++) {
                const int kh = t / 3, kw = t % 3;
                float4 wv = w_s[(ci * 9 + t) * 16 + cg];
                #pragma unroll
                for (int i = 0; i < 2; i++)
                    #pragma unroll
                    for (int j = 0; j < 2; j++) {
                        float xx = xv[i + kh][j + kw];
                        acc[0][i][j] = fmaf(wv.x, xx, acc[0][i][j]);
                        acc[1][i][j] = fmaf(wv.y, xx, acc[1][i][j]);
                        acc[2][i][j] = fmaf(wv.z, xx, acc[2][i][j]);
                        acc[3][i][j] = fmaf(wv.w, xx, acc[3][i][j]);
                    }
            }
        }
        __syncthreads();
    }

    const int ob = o0 + cg * 4;
    #pragma unroll
    for (int oi = 0; oi < 4; oi++) {
        float* op = out + ((size_t)(b * COUT + ob + oi)) * HWSZ;
        #pragma unroll
        for (int i = 0; i < 2; i++)
            #pragma unroll
            for (int j = 0; j < 2; j++)
                op[(h0 + pr + i) * WW + (w0 + pc + j)] = acc[oi][i][j];
    }
}

// ---------------------------------------------------------------------------
extern "C" void kernel_launch(void* const* d_in, const int* in_sizes, int n_in,
                              void* d_out, int out_size) {
    const float* x      = (const float*)d_in[0];  // (32,256,56,56)
    const float* att_w  = (const float*)d_in[1];  // (4,256)
    const float* weight = (const float*)d_in[2];  // (4,256,256,3,3)
    float* out = (float*)d_out;                   // (32,256,56,56)

    mean_kernel<<<BATCH * CIN, 256>>>(x);
    att_kernel<<<1, 128>>>(att_w);
    agg_kernel<<<dim3(CIN, BATCH), 256>>>(weight);
    conv_kernel<<<dim3(49, 4, BATCH), 256>>>(x, out);
}

// round 2
// speedup vs baseline: 1.0651x; 1.0651x over previous
#include <cuda_runtime.h>
#include <math.h>

#define BATCH 32
#define CIN   256
#define COUT  256
#define NEXP  4
#define HH    56
#define WW    56
#define HWSZ  3136

typedef unsigned long long ull;

// f32x2 packed FMA: d = a*b + c  (elementwise on two packed fp32)
#define FMA_F32X2(d, a, b, c) \
    asm("fma.rn.f32x2 %0, %1, %2, %3;" : "=l"(d) : "l"(a), "l"(b), "l"(c))
// duplicate a scalar float into both halves of an f32x2
#define DUP_F32X2(d, x) \
    asm("mov.b64 %0, {%1, %1};" : "=l"(d) : "f"(x))
#define UNPACK_F32X2(lo, hi, v) \
    asm("mov.b64 {%0, %1}, %2;" : "=f"(lo), "=f"(hi) : "l"(v))

// Scratch (allocation-free rule: __device__ globals)
__device__ float g_pooled[BATCH * CIN];
__device__ float g_att[BATCH * NEXP];
// agg[b][ci][t][o]  (o contiguous -> LDS.128 over 4 couts in conv kernel)
__device__ float g_aggw[(size_t)BATCH * CIN * 9 * COUT];

// ---------------------------------------------------------------------------
// Kernel 1: per-(b,c) spatial mean.
// ---------------------------------------------------------------------------
__global__ void mean_kernel(const float* __restrict__ x) {
    int bc = blockIdx.x;
    const float4* p = reinterpret_cast<const float4*>(x + (size_t)bc * HWSZ);
    float s = 0.f;
    for (int i = threadIdx.x; i < HWSZ / 4; i += 256) {
        float4 v = p[i];
        s += (v.x + v.y) + (v.z + v.w);
    }
    #pragma unroll
    for (int o = 16; o; o >>= 1) s += __shfl_xor_sync(0xffffffffu, s, o);
    __shared__ float ws[8];
    if ((threadIdx.x & 31) == 0) ws[threadIdx.x >> 5] = s;
    __syncthreads();
    if (threadIdx.x == 0) {
        float t = 0.f;
        #pragma unroll
        for (int i = 0; i < 8; i++) t += ws[i];
        g_pooled[bc] = t * (1.0f / (float)HWSZ);
    }
}

// ---------------------------------------------------------------------------
// Kernel 2: att[b][k] = sigmoid(pooled[b] . att_w[k])
// ---------------------------------------------------------------------------
__global__ void att_kernel(const float* __restrict__ att_w) {
    int idx = threadIdx.x;           // b*4 + k
    int b = idx >> 2, k = idx & 3;
    const float* pr = g_pooled + b * CIN;
    const float* wr = att_w + k * CIN;
    float s = 0.f;
    #pragma unroll 8
    for (int c = 0; c < CIN; c++) s += pr[c] * wr[c];
    g_att[idx] = 1.0f / (1.0f + expf(-s));
}

// ---------------------------------------------------------------------------
// Kernel 3: agg[b][ci][t][o] = sum_k att[b,k] * w[k][o][ci][t]
// ---------------------------------------------------------------------------
__global__ void agg_kernel(const float* __restrict__ weight) {
    int ci = blockIdx.x;
    int b  = blockIdx.y;
    int o  = threadIdx.x;
    float acc[9];
    #pragma unroll
    for (int t = 0; t < 9; t++) acc[t] = 0.f;
    #pragma unroll
    for (int k = 0; k < NEXP; k++) {
        float a = g_att[b * NEXP + k];
        const float* wp = weight + (((size_t)(k * COUT + o)) * CIN + ci) * 9;
        #pragma unroll
        for (int t = 0; t < 9; t++) acc[t] += a * wp[t];
    }
    float* op = g_aggw + ((size_t)(b * CIN + ci)) * 9 * COUT + o;
    #pragma unroll
    for (int t = 0; t < 9; t++) op[t * COUT] = acc[t];
}

// ---------------------------------------------------------------------------
// Kernel 4: direct conv, FFMA2 version.
// Block tile: 64 couts x (8x8) pixels, 256 threads.
// Per-thread: 4 couts x (2x2) pixels; couts packed pairwise into f32x2.
// x_s row stride = 20 floats -> LDS.64 x loads are bank-conflict-free.
// ---------------------------------------------------------------------------
#define XS_CI  200   // 10 rows * 20 floats
#define XS_ROW 20

__global__ void __launch_bounds__(256) conv_kernel(const float* __restrict__ x,
                                                   float* __restrict__ out) {
    __shared__ float  x_s[8 * XS_CI];    // 8 ci x 10 rows x 20-stride (10 used)
    __shared__ float4 w_s[72 * 16];      // [ci*9+t][16 x float4] = 64 couts

    const int b   = blockIdx.z;
    const int o0  = blockIdx.y * 64;
    const int sp  = blockIdx.x;
    const int h0  = (sp / 7) * 8;
    const int w0  = (sp % 7) * 8;
    const int tid = threadIdx.x;
    const int pix = tid & 15;            // 4x4 grid of 2x2 pixel blocks
    const int cg  = tid >> 4;            // cout group-of-4 (0..15)
    const int pr  = (pix >> 2) * 2;
    const int pc  = (pix & 3) * 2;

    // acc[oi2][i][j]: oi2=0 -> couts (0,1), oi2=1 -> couts (2,3), packed f32x2
    ull acc[2][2][2];
    #pragma unroll
    for (int oi = 0; oi < 2; oi++)
        #pragma unroll
        for (int i = 0; i < 2; i++)
            #pragma unroll
            for (int j = 0; j < 2; j++) acc[oi][i][j] = 0ull;

    const float* xb = x + (size_t)b * CIN * HWSZ;

    for (int ci0 = 0; ci0 < CIN; ci0 += 8) {
        // --- stage x halo tile (zero-padded), padded row stride 20 ---
        for (int idx = tid; idx < 800; idx += 256) {
            int ci  = idx / 100;
            int rem = idx - ci * 100;
            int r   = rem / 10;
            int c   = rem - r * 10;
            int hh  = h0 + r - 1;
            int ww  = w0 + c - 1;
            float v = 0.f;
            if (hh >= 0 && hh < HH && ww >= 0 && ww < WW)
                v = xb[(size_t)(ci0 + ci) * HWSZ + hh * WW + ww];
            x_s[ci * XS_CI + r * XS_ROW + c] = v;
        }
        // --- stage aggregated weights: 72 rows x 64 couts (1152 float4) ---
        const float4* wg = reinterpret_cast<const float4*>(
            g_aggw + ((size_t)(b * CIN + ci0)) * 9 * COUT + o0);
        for (int f = tid; f < 1152; f += 256) {
            int row = f >> 4;            // ci*9 + t
            int q   = f & 15;
            w_s[f] = wg[row * 64 + q];   // global row pitch = 256 floats
        }
        __syncthreads();

        #pragma unroll
        for (int ci = 0; ci < 8; ci++) {
            // load 4x4 patch as float2 (conflict-free), dup into f32x2 pairs
            ull xd[4][4];
            #pragma unroll
            for (int rr = 0; rr < 4; rr++) {
                const float* rowp = &x_s[ci * XS_CI + (pr + rr) * XS_ROW + pc];
                float2 v0 = *reinterpret_cast<const float2*>(rowp);
                float2 v1 = *reinterpret_cast<const float2*>(rowp + 2);
                DUP_F32X2(xd[rr][0], v0.x);
                DUP_F32X2(xd[rr][1], v0.y);
                DUP_F32X2(xd[rr][2], v1.x);
                DUP_F32X2(xd[rr][3], v1.y);
            }
            #pragma unroll
            for (int t = 0; t < 9; t++) {
                const int kh = t / 3, kw = t % 3;
                // float4 weight = two naturally-aligned f32x2 pairs
                ulonglong2 wv = *reinterpret_cast<const ulonglong2*>(
                    &w_s[(ci * 9 + t) * 16 + cg]);
                #pragma unroll
                for (int i = 0; i < 2; i++)
                    #pragma unroll
                    for (int j = 0; j < 2; j++) {
                        ull xx = xd[i + kh][j + kw];
                        FMA_F32X2(acc[0][i][j], wv.x, xx, acc[0][i][j]);
                        FMA_F32X2(acc[1][i][j], wv.y, xx, acc[1][i][j]);
                    }
            }
        }
        __syncthreads();
    }

    const int ob = o0 + cg * 4;
    #pragma unroll
    for (int oi = 0; oi < 2; oi++) {
        float* op0 = out + ((size_t)(b * COUT + ob + oi * 2 + 0)) * HWSZ;
        float* op1 = out + ((size_t)(b * COUT + ob + oi * 2 + 1)) * HWSZ;
        #pragma unroll
        for (int i = 0; i < 2; i++)
            #pragma unroll
            for (int j = 0; j < 2; j++) {
                float lo, hi;
                UNPACK_F32X2(lo, hi, acc[oi][i][j]);
                op0[(h0 + pr + i) * WW + (w0 + pc + j)] = lo;
                op1[(h0 + pr + i) * WW + (w0 + pc + j)] = hi;
            }
    }
}

// ---------------------------------------------------------------------------
extern "C" void kernel_launch(void* const* d_in, const int* in_sizes, int n_in,
                              void* d_out, int out_size) {
    const float* x      = (const float*)d_in[0];  // (32,256,56,56)
    const float* att_w  = (const float*)d_in[1];  // (4,256)
    const float* weight = (const float*)d_in[2];  // (4,256,256,3,3)
    float* out = (float*)d_out;                   // (32,256,56,56)

    mean_kernel<<<BATCH * CIN, 256>>>(x);
    att_kernel<<<1, 128>>>(att_w);
    agg_kernel<<<dim3(CIN, BATCH), 256>>>(weight);
    conv_kernel<<<dim3(49, 4, BATCH), 256>>>(x, out);
}

// round 4
// speedup vs baseline: 2.5228x; 2.3686x over previous
#include <cuda_runtime.h>
#include <cuda_bf16.h>
#include <math.h>
#include <stdint.h>

#define BATCH 32
#define CIN   256
#define COUT  256
#define NEXP  4
#define HH    56
#define WW    56
#define HWSZ  3136

#define PADW    58
#define QCNT    3364           // 58*58 padded positions
#define GUARD   64
#define ROWSPAD 3712           // GUARD + 28*128 + GUARD
#define MTILES  27             // ceil(3364/128)

// ---------------------------------------------------------------------------
// Scratch (__device__ globals zero-initialized; guard/border rows stay 0)
// ---------------------------------------------------------------------------
__device__ float g_pooled[BATCH * CIN];
__device__ float g_att[BATCH * NEXP];
__device__ __nv_bfloat16 g_xt_hi[(size_t)BATCH * ROWSPAD * CIN];
__device__ __nv_bfloat16 g_xt_lo[(size_t)BATCH * ROWSPAD * CIN];
__device__ __nv_bfloat16 g_wb_hi[(size_t)BATCH * 9 * COUT * CIN];
__device__ __nv_bfloat16 g_wb_lo[(size_t)BATCH * 9 * COUT * CIN];

// ---------------------------------------------------------------------------
// PTX helpers (all compute_80-era: valid on compute_103 base target)
// ---------------------------------------------------------------------------
__device__ __forceinline__ uint32_t smem_u32(const void* p) {
    uint32_t a;
    asm("{ .reg .u64 t; cvta.to.shared.u64 t, %1; cvt.u32.u64 %0, t; }"
        : "=r"(a) : "l"(p));
    return a;
}
#define CP_ASYNC16(dst, src) \
    asm volatile("cp.async.cg.shared.global [%0], [%1], 16;" \
                 :: "r"(dst), "l"(src) : "memory")
#define CP_COMMIT() asm volatile("cp.async.commit_group;" ::: "memory")
#define CP_WAIT0()  asm volatile("cp.async.wait_group 0;" ::: "memory")
#define CP_WAIT1()  asm volatile("cp.async.wait_group 1;" ::: "memory")

#define LDSM4(r, addr) \
    asm volatile("ldmatrix.sync.aligned.m8n8.x4.shared.b16 {%0,%1,%2,%3}, [%4];" \
                 : "=r"((r)[0]), "=r"((r)[1]), "=r"((r)[2]), "=r"((r)[3]) \
                 : "r"(addr))

#define MMA16816(d, a, b0, b1) \
    asm volatile("mma.sync.aligned.m16n8k16.row.col.f32.bf16.bf16.f32 " \
                 "{%0,%1,%2,%3}, {%4,%5,%6,%7}, {%8,%9}, {%0,%1,%2,%3};" \
                 : "+f"((d)[0]), "+f"((d)[1]), "+f"((d)[2]), "+f"((d)[3]) \
                 : "r"((a)[0]), "r"((a)[1]), "r"((a)[2]), "r"((a)[3]), \
                   "r"(b0), "r"(b1))

// ---------------------------------------------------------------------------
// Kernel 1: per-(b,c) spatial mean
// ---------------------------------------------------------------------------
__global__ void mean_kernel(const float* __restrict__ x) {
    int bc = blockIdx.x;
    const float4* p = reinterpret_cast<const float4*>(x + (size_t)bc * HWSZ);
    float s = 0.f;
    for (int i = threadIdx.x; i < HWSZ / 4; i += 256) {
        float4 v = p[i];
        s += (v.x + v.y) + (v.z + v.w);
    }
    #pragma unroll
    for (int o = 16; o; o >>= 1) s += __shfl_xor_sync(0xffffffffu, s, o);
    __shared__ float ws[8];
    if ((threadIdx.x & 31) == 0) ws[threadIdx.x >> 5] = s;
    __syncthreads();
    if (threadIdx.x == 0) {
        float t = 0.f;
        #pragma unroll
        for (int i = 0; i < 8; i++) t += ws[i];
        g_pooled[bc] = t * (1.0f / (float)HWSZ);
    }
}

// ---------------------------------------------------------------------------
// Kernel 2: att = sigmoid(pooled @ att_w^T)
// ---------------------------------------------------------------------------
__global__ void att_kernel(const float* __restrict__ att_w) {
    int idx = threadIdx.x;
    int b = idx >> 2, k = idx & 3;
    const float* pr = g_pooled + b * CIN;
    const float* wr = att_w + k * CIN;
    float s = 0.f;
    #pragma unroll 8
    for (int c = 0; c < CIN; c++) s += pr[c] * wr[c];
    g_att[idx] = 1.0f / (1.0f + expf(-s));
}

// ---------------------------------------------------------------------------
// Kernel 3: aggregate weights -> bf16 hi/lo, layout [b][t][cout][ci]
// ---------------------------------------------------------------------------
__global__ void wprep_kernel(const float* __restrict__ weight) {
    int o = blockIdx.x, b = blockIdx.y, ci = threadIdx.x;
    float a[NEXP];
    #pragma unroll
    for (int k = 0; k < NEXP; k++) a[k] = g_att[b * NEXP + k];
    #pragma unroll
    for (int t = 0; t < 9; t++) {
        float v = 0.f;
        #pragma unroll
        for (int k = 0; k < NEXP; k++)
            v += a[k] * weight[(((size_t)k * COUT + o) * CIN + ci) * 9 + t];
        __nv_bfloat16 hi = __float2bfloat16(v);
        __nv_bfloat16 lo = __float2bfloat16(v - __bfloat162float(hi));
        size_t p = (((size_t)b * 9 + t) * COUT + o) * CIN + ci;
        g_wb_hi[p] = hi;
        g_wb_lo[p] = lo;
    }
}

// ---------------------------------------------------------------------------
// Kernel 4: transpose x -> padded position-major bf16 hi/lo
// ---------------------------------------------------------------------------
__global__ void __launch_bounds__(256) transpose_kernel(const float* __restrict__ x) {
    __shared__ float tile[64][33];
    int b   = blockIdx.z;
    int ci0 = blockIdx.y * 64;
    int p0  = blockIdx.x * 32;
    int tid = threadIdx.x;
    int px = tid & 31, cir = tid >> 5;
    #pragma unroll
    for (int i = 0; i < 8; i++) {
        int ci = cir * 8 + i;
        tile[ci][px] = x[((size_t)b * CIN + ci0 + ci) * HWSZ + p0 + px];
    }
    __syncthreads();
    int cc = tid & 7, r = tid >> 3;
    int p = p0 + r;
    int h = p / WW, w = p % WW;
    size_t row = (size_t)b * ROWSPAD + GUARD + (size_t)(h + 1) * PADW + (w + 1);
    __align__(16) __nv_bfloat16 hi8[8];
    __align__(16) __nv_bfloat16 lo8[8];
    #pragma unroll
    for (int j = 0; j < 8; j++) {
        float v = tile[cc * 8 + j][r];
        __nv_bfloat16 hv = __float2bfloat16(v);
        hi8[j] = hv;
        lo8[j] = __float2bfloat16(v - __bfloat162float(hv));
    }
    *reinterpret_cast<uint4*>(g_xt_hi + row * CIN + ci0 + cc * 8) =
        *reinterpret_cast<const uint4*>(hi8);
    *reinterpret_cast<uint4*>(g_xt_lo + row * CIN + ci0 + cc * 8) =
        *reinterpret_cast<const uint4*>(lo8);
}

// ---------------------------------------------------------------------------
// Kernel 5: implicit-GEMM conv via mma.sync.m16n8k16 (bf16 3-combo split).
// CTA tile: 128 positions x 128 couts. 8 warps = 4(M) x 2(N), warp 32x64.
// K loop: 36 stages (9 taps x 4 ci-chunks of 64), cp.async double-buffered.
// SMEM stage (64KB): A_hi|A_lo [128x64] + B_hi|B_lo [128x64], xor-swizzled.
// ---------------------------------------------------------------------------
#define STG_BYTES 65536
#define SMEM_BYTES_MMA (2 * STG_BYTES)
#define SWZ_RC(r, c) ((uint32_t)((r) * 128 + (((c) ^ ((r) & 7)) << 4)))

__global__ void __launch_bounds__(256, 1) conv_mma(float* __restrict__ out) {
    extern __shared__ char smem[];
    const uint32_t sbase = smem_u32(smem);
    const int tid = threadIdx.x, wid = tid >> 5, lid = tid & 31;
    const int b  = blockIdx.y;
    const int mt = blockIdx.x >> 1, nt = blockIdx.x & 1;
    const int q0 = mt * 128, n0 = nt * 128;
    const int mwarp = wid >> 1, nwarp = wid & 1;

    const __nv_bfloat16* xsrc[2] = {g_xt_hi + (size_t)b * ROWSPAD * CIN,
                                    g_xt_lo + (size_t)b * ROWSPAD * CIN};
    const __nv_bfloat16* wsrc[2] = {g_wb_hi + (size_t)b * 9 * COUT * CIN,
                                    g_wb_lo + (size_t)b * 9 * COUT * CIN};

    float acc[2][8][4];
    #pragma unroll
    for (int mi = 0; mi < 2; mi++)
        #pragma unroll
        for (int ni = 0; ni < 8; ni++)
            #pragma unroll
            for (int e = 0; e < 4; e++) acc[mi][ni][e] = 0.f;

    // ---- stage issuer: 16 cp.async(16B) per thread per stage ----
    auto issue = [&](int s) {
        const int t = s >> 2, ci0 = (s & 3) << 6;
        const int off = (t / 3 - 1) * PADW + (t % 3 - 1);
        const int abase = GUARD + q0 + off;
        const uint32_t stg = sbase + (uint32_t)(s & 1) * STG_BYTES;
        #pragma unroll
        for (int i = 0; i < 8; i++) {           // A: 2 splits x 128r x 8c
            int j = tid + i * 256;
            int sp = j >> 10, r = (j >> 3) & 127, c = j & 7;
            const __nv_bfloat16* src =
                xsrc[sp] + (size_t)(abase + r) * CIN + ci0 + c * 8;
            CP_ASYNC16(stg + sp * 16384 + SWZ_RC(r, c), src);
        }
        #pragma unroll
        for (int i = 0; i < 8; i++) {           // B: 2 splits x 128n x 8c
            int j = tid + i * 256;
            int sp = j >> 10, r = (j >> 3) & 127, c = j & 7;
            const __nv_bfloat16* src =
                wsrc[sp] + ((size_t)t * COUT + n0 + r) * CIN + ci0 + c * 8;
            CP_ASYNC16(stg + 32768 + sp * 16384 + SWZ_RC(r, c), src);
        }
        CP_COMMIT();
    };

    issue(0);

    const int lr = lid & 15, lc = lid >> 4;     // ldmatrix address lanes

    for (int s = 0; s < 36; s++) {
        if (s + 1 < 36) { issue(s + 1); CP_WAIT1(); }
        else           { CP_WAIT0(); }
        __syncthreads();

        const uint32_t Abuf = sbase + (uint32_t)(s & 1) * STG_BYTES;
        const uint32_t Bbuf = Abuf + 32768;

        #pragma unroll
        for (int k16 = 0; k16 < 4; k16++) {
            // A fragments, both splits (hi=0, lo=1)
            uint32_t af[2][2][4];
            #pragma unroll
            for (int sp = 0; sp < 2; sp++)
                #pragma unroll
                for (int mi = 0; mi < 2; mi++) {
                    int row = mwarp * 32 + mi * 16 + lr;
                    uint32_t addr = Abuf + sp * 16384 + row * 128 +
                                    ((uint32_t)((k16 * 2 + lc) ^ (row & 7)) << 4);
                    LDSM4(af[sp][mi], addr);
                }
            // B hi fragments
            uint32_t bf[4][4];
            #pragma unroll
            for (int ni = 0; ni < 4; ni++) {
                int row = nwarp * 64 + ni * 16 + lr;
                uint32_t addr = Bbuf + row * 128 +
                                ((uint32_t)((k16 * 2 + lc) ^ (row & 7)) << 4);
                LDSM4(bf[ni], addr);
            }
            // combos: Xhi*Whi and Xlo*Whi
            #pragma unroll
            for (int mi = 0; mi < 2; mi++)
                #pragma unroll
                for (int ni = 0; ni < 4; ni++) {
                    MMA16816(acc[mi][2 * ni + 0], af[0][mi], bf[ni][0], bf[ni][2]);
                    MMA16816(acc[mi][2 * ni + 1], af[0][mi], bf[ni][1], bf[ni][3]);
                    MMA16816(acc[mi][2 * ni + 0], af[1][mi], bf[ni][0], bf[ni][2]);
                    MMA16816(acc[mi][2 * ni + 1], af[1][mi], bf[ni][1], bf[ni][3]);
                }
            // B lo fragments
            #pragma unroll
            for (int ni = 0; ni < 4; ni++) {
                int row = nwarp * 64 + ni * 16 + lr;
                uint32_t addr = Bbuf + 16384 + row * 128 +
                                ((uint32_t)((k16 * 2 + lc) ^ (row & 7)) << 4);
                LDSM4(bf[ni], addr);
            }
            // combo: Xhi*Wlo
            #pragma unroll
            for (int mi = 0; mi < 2; mi++)
                #pragma unroll
                for (int ni = 0; ni < 4; ni++) {
                    MMA16816(acc[mi][2 * ni + 0], af[0][mi], bf[ni][0], bf[ni][2]);
                    MMA16816(acc[mi][2 * ni + 1], af[0][mi], bf[ni][1], bf[ni][3]);
                }
        }
        __syncthreads();   // buffer (s&1) free for issue(s+2)
    }

    // ---- epilogue: scatter acc to out[b][cout][h*56+w] ----
    const int gr = lid >> 2, c2 = (lid & 3) * 2;
    float* outb = out + (size_t)b * COUT * HWSZ;
    #pragma unroll
    for (int mi = 0; mi < 2; mi++) {
        int qa = q0 + mwarp * 32 + mi * 16 + gr;
        int qb = qa + 8;
        int ha = qa / PADW - 1, wa = qa % PADW - 1;
        int hb = qb / PADW - 1, wb = qb % PADW - 1;
        bool va = ((unsigned)ha < HH) && ((unsigned)wa < WW);
        bool vb = ((unsigned)hb < HH) && ((unsigned)wb < WW);
        int pa = ha * WW + wa, pb = hb * WW + wb;
        #pragma unroll
        for (int ni = 0; ni < 8; ni++) {
            int n = n0 + nwarp * 64 + ni * 8 + c2;
            float* p = outb + (size_t)n * HWSZ;
            if (va) { p[pa] = acc[mi][ni][0]; p[HWSZ + pa] = acc[mi][ni][1]; }
            if (vb) { p[pb] = acc[mi][ni][2]; p[HWSZ + pb] = acc[mi][ni][3]; }
        }
    }
}

// ---------------------------------------------------------------------------
extern "C" void kernel_launch(void* const* d_in, const int* in_sizes, int n_in,
                              void* d_out, int out_size) {
    const float* x      = (const float*)d_in[0];  // (32,256,56,56)
    const float* att_w  = (const float*)d_in[1];  // (4,256)
    const float* weight = (const float*)d_in[2];  // (4,256,256,3,3)
    float* out = (float*)d_out;                   // (32,256,56,56)

    cudaFuncSetAttribute(conv_mma, cudaFuncAttributeMaxDynamicSharedMemorySize,
                         SMEM_BYTES_MMA);

    mean_kernel<<<BATCH * CIN, 256>>>(x);
    att_kernel<<<1, 128>>>(att_w);
    wprep_kernel<<<dim3(COUT, BATCH), 256>>>(weight);
    transpose_kernel<<<dim3(98, 4, BATCH), 256>>>(x);
    conv_mma<<<dim3(MTILES * 2, BATCH), 256, SMEM_BYTES_MMA>>>(out);
}

// round 5
// speedup vs baseline: 2.7748x; 1.0999x over previous
#include <cuda_runtime.h>
#include <cuda_bf16.h>
#include <math.h>
#include <stdint.h>

#define BATCH 32
#define CIN   256
#define COUT  256
#define NEXP  4
#define HH    56
#define WW    56
#define HWSZ  3136

#define PADW    58
#define QCNT    3364           // 58*58 padded positions
#define GUARD   64
#define ROWSPAD 3712           // GUARD + 28*128 + GUARD
#define MTILES  27             // ceil(3364/128)

// ---------------------------------------------------------------------------
// Scratch (__device__ globals zero-initialized; guard/border rows stay 0)
// ---------------------------------------------------------------------------
__device__ float g_pooled[BATCH * CIN];
__device__ float g_att[BATCH * NEXP];
__device__ __nv_bfloat16 g_xt_hi[(size_t)BATCH * ROWSPAD * CIN];
__device__ __nv_bfloat16 g_xt_lo[(size_t)BATCH * ROWSPAD * CIN];
__device__ __nv_bfloat16 g_wb_hi[(size_t)BATCH * 9 * COUT * CIN];
__device__ __nv_bfloat16 g_wb_lo[(size_t)BATCH * 9 * COUT * CIN];

// ---------------------------------------------------------------------------
// PTX helpers (compute_80-era: valid on compute_103 base target)
// ---------------------------------------------------------------------------
__device__ __forceinline__ uint32_t smem_u32(const void* p) {
    uint32_t a;
    asm("{ .reg .u64 t; cvta.to.shared.u64 t, %1; cvt.u32.u64 %0, t; }"
        : "=r"(a) : "l"(p));
    return a;
}
#define CP_ASYNC16(dst, src) \
    asm volatile("cp.async.cg.shared.global [%0], [%1], 16;" \
                 :: "r"(dst), "l"(src) : "memory")
#define CP_COMMIT() asm volatile("cp.async.commit_group;" ::: "memory")
#define CP_WAIT0()  asm volatile("cp.async.wait_group 0;" ::: "memory")
#define CP_WAIT1()  asm volatile("cp.async.wait_group 1;" ::: "memory")

#define LDSM4(r, addr) \
    asm volatile("ldmatrix.sync.aligned.m8n8.x4.shared.b16 {%0,%1,%2,%3}, [%4];" \
                 : "=r"((r)[0]), "=r"((r)[1]), "=r"((r)[2]), "=r"((r)[3]) \
                 : "r"(addr))

#define MMA16816(d, a, b0, b1) \
    asm volatile("mma.sync.aligned.m16n8k16.row.col.f32.bf16.bf16.f32 " \
                 "{%0,%1,%2,%3}, {%4,%5,%6,%7}, {%8,%9}, {%0,%1,%2,%3};" \
                 : "+f"((d)[0]), "+f"((d)[1]), "+f"((d)[2]), "+f"((d)[3]) \
                 : "r"((a)[0]), "r"((a)[1]), "r"((a)[2]), "r"((a)[3]), \
                   "r"(b0), "r"(b1))

// ---------------------------------------------------------------------------
// Kernel 1: per-(b,c) spatial mean
// ---------------------------------------------------------------------------
__global__ void mean_kernel(const float* __restrict__ x) {
    int bc = blockIdx.x;
    const float4* p = reinterpret_cast<const float4*>(x + (size_t)bc * HWSZ);
    float s = 0.f;
    for (int i = threadIdx.x; i < HWSZ / 4; i += 256) {
        float4 v = p[i];
        s += (v.x + v.y) + (v.z + v.w);
    }
    #pragma unroll
    for (int o = 16; o; o >>= 1) s += __shfl_xor_sync(0xffffffffu, s, o);
    __shared__ float ws[8];
    if ((threadIdx.x & 31) == 0) ws[threadIdx.x >> 5] = s;
    __syncthreads();
    if (threadIdx.x == 0) {
        float t = 0.f;
        #pragma unroll
        for (int i = 0; i < 8; i++) t += ws[i];
        g_pooled[bc] = t * (1.0f / (float)HWSZ);
    }
}

// ---------------------------------------------------------------------------
// Kernel 2: att = sigmoid(pooled @ att_w^T)
// ---------------------------------------------------------------------------
__global__ void att_kernel(const float* __restrict__ att_w) {
    int idx = threadIdx.x;
    int b = idx >> 2, k = idx & 3;
    const float* pr = g_pooled + b * CIN;
    const float* wr = att_w + k * CIN;
    float s = 0.f;
    #pragma unroll 8
    for (int c = 0; c < CIN; c++) s += pr[c] * wr[c];
    g_att[idx] = 1.0f / (1.0f + expf(-s));
}

// ---------------------------------------------------------------------------
// Kernel 3: aggregate weights -> bf16 hi/lo, layout [b][t][cout][ci]
// ---------------------------------------------------------------------------
__global__ void wprep_kernel(const float* __restrict__ weight) {
    int o = blockIdx.x, b = blockIdx.y, ci = threadIdx.x;
    float a[NEXP];
    #pragma unroll
    for (int k = 0; k < NEXP; k++) a[k] = g_att[b * NEXP + k];
    #pragma unroll
    for (int t = 0; t < 9; t++) {
        float v = 0.f;
        #pragma unroll
        for (int k = 0; k < NEXP; k++)
            v += a[k] * weight[(((size_t)k * COUT + o) * CIN + ci) * 9 + t];
        __nv_bfloat16 hi = __float2bfloat16(v);
        __nv_bfloat16 lo = __float2bfloat16(v - __bfloat162float(hi));
        size_t p = (((size_t)b * 9 + t) * COUT + o) * CIN + ci;
        g_wb_hi[p] = hi;
        g_wb_lo[p] = lo;
    }
}

// ---------------------------------------------------------------------------
// Kernel 4: transpose x -> padded position-major bf16 hi/lo
// ---------------------------------------------------------------------------
__global__ void __launch_bounds__(256) transpose_kernel(const float* __restrict__ x) {
    __shared__ float tile[64][33];
    int b   = blockIdx.z;
    int ci0 = blockIdx.y * 64;
    int p0  = blockIdx.x * 32;
    int tid = threadIdx.x;
    int px = tid & 31, cir = tid >> 5;
    #pragma unroll
    for (int i = 0; i < 8; i++) {
        int ci = cir * 8 + i;
        tile[ci][px] = x[((size_t)b * CIN + ci0 + ci) * HWSZ + p0 + px];
    }
    __syncthreads();
    int cc = tid & 7, r = tid >> 3;
    int p = p0 + r;
    int h = p / WW, w = p % WW;
    size_t row = (size_t)b * ROWSPAD + GUARD + (size_t)(h + 1) * PADW + (w + 1);
    __align__(16) __nv_bfloat16 hi8[8];
    __align__(16) __nv_bfloat16 lo8[8];
    #pragma unroll
    for (int j = 0; j < 8; j++) {
        float v = tile[cc * 8 + j][r];
        __nv_bfloat16 hv = __float2bfloat16(v);
        hi8[j] = hv;
        lo8[j] = __float2bfloat16(v - __bfloat162float(hv));
    }
    *reinterpret_cast<uint4*>(g_xt_hi + row * CIN + ci0 + cc * 8) =
        *reinterpret_cast<const uint4*>(hi8);
    *reinterpret_cast<uint4*>(g_xt_lo + row * CIN + ci0 + cc * 8) =
        *reinterpret_cast<const uint4*>(lo8);
}

// ---------------------------------------------------------------------------
// Kernel 5: implicit-GEMM conv, mma.sync bf16 3-combo split.
// CTA tile: M=128 positions x N=256 couts, 512 threads (16 warps = 4M x 4N).
// A (x) staged once per ci-chunk as a 256-row halo; all 9 taps are row
// offsets into the resident halo. B (w) staged per (chunk,tap), 2 buffers.
// SMEM: A halo 64KB | B stage0 64KB | B stage1 64KB  = 192KB.
// ---------------------------------------------------------------------------
#define A_BYTES   65536
#define B_STG     65536
#define SMEM_BYTES_MMA (A_BYTES + 2 * B_STG)
#define SWZ_RC(r, c) ((uint32_t)((r) * 128 + (((c) ^ ((r) & 7)) << 4)))

__global__ void __launch_bounds__(512, 1) conv_mma(float* __restrict__ out) {
    extern __shared__ char smem[];
    const uint32_t sbase = smem_u32(smem);
    const int tid = threadIdx.x, wid = tid >> 5, lid = tid & 31;
    const int b  = blockIdx.y;
    const int q0 = blockIdx.x * 128;
    const int mwarp = wid >> 2, nwarp = wid & 3;

    const __nv_bfloat16* xsrc[2] = {g_xt_hi + (size_t)b * ROWSPAD * CIN,
                                    g_xt_lo + (size_t)b * ROWSPAD * CIN};
    const __nv_bfloat16* wsrc[2] = {g_wb_hi + (size_t)b * 9 * COUT * CIN,
                                    g_wb_lo + (size_t)b * 9 * COUT * CIN};

    float acc[2][8][4];
    #pragma unroll
    for (int mi = 0; mi < 2; mi++)
        #pragma unroll
        for (int ni = 0; ni < 8; ni++)
            #pragma unroll
            for (int e = 0; e < 4; e++) acc[mi][ni][e] = 0.f;

    // ---- A halo: 2 splits x 256 rows x 64 ci, global rows [q0, q0+256) of
    //      xt (= padded rows GUARD+q0-64 ...), 8 cp.async(16B)/thread ----
    auto issueA = [&](int c4) {
        const int ci0 = c4 << 6;
        #pragma unroll
        for (int i = 0; i < 8; i++) {
            int j = tid + i * 512;
            int sp = j >> 11, r = (j >> 3) & 255, c = j & 7;
            const __nv_bfloat16* src =
                xsrc[sp] + (size_t)(q0 + r) * CIN + ci0 + c * 8;
            CP_ASYNC16(sbase + sp * 32768 + SWZ_RC(r, c), src);
        }
        CP_COMMIT();
    };
    // ---- B stage: 2 splits x 256 n x 64 ci for tap t, chunk c4 ----
    auto issueB = [&](int s) {
        const int t = s / 4, ci0 = (s & 3) << 6;   // s = c4*... NO: s = t major
        (void)t; (void)ci0;
    };
    (void)issueB;

    // stage order: s = c4*9 + t  (chunk-major so A is loaded once per chunk)
    auto issueBs = [&](int s) {
        const int c4 = s / 9, t = s - c4 * 9;
        const int ci0 = c4 << 6;
        const uint32_t stg = sbase + A_BYTES + (uint32_t)(s & 1) * B_STG;
        #pragma unroll
        for (int i = 0; i < 8; i++) {
            int j = tid + i * 512;
            int sp = j >> 11, r = (j >> 3) & 255, c = j & 7;
            const __nv_bfloat16* src =
                wsrc[sp] + ((size_t)t * COUT + r) * CIN + ci0 + c * 8;
            CP_ASYNC16(stg + sp * 32768 + SWZ_RC(r, c), src);
        }
        CP_COMMIT();
    };

    issueA(0);
    issueBs(0);

    const int lr = lid & 15, lc = lid >> 4;

    for (int s = 0; s < 36; s++) {
        const int c4 = s / 9, t = s - c4 * 9;
        if (t == 0 && s > 0) issueA(c4);          // A buffer free: prev chunk done
        if (s + 1 < 36) { issueBs(s + 1); CP_WAIT1(); }
        else            { CP_WAIT0(); }
        __syncthreads();

        const int off = (t / 3 - 1) * PADW + (t % 3 - 1);
        const int arow0 = 64 + off + mwarp * 32;  // row in halo
        const uint32_t Bhi = sbase + A_BYTES + (uint32_t)(s & 1) * B_STG;

        #pragma unroll
        for (int k16 = 0; k16 < 4; k16++) {
            uint32_t af[2][2][4];
            #pragma unroll
            for (int sp = 0; sp < 2; sp++)
                #pragma unroll
                for (int mi = 0; mi < 2; mi++) {
                    int row = arow0 + mi * 16 + lr;
                    uint32_t addr = sbase + sp * 32768 + row * 128 +
                                    ((uint32_t)((k16 * 2 + lc) ^ (row & 7)) << 4);
                    LDSM4(af[sp][mi], addr);
                }
            uint32_t bf[4][4];
            #pragma unroll
            for (int ni = 0; ni < 4; ni++) {
                int row = nwarp * 64 + ni * 16 + lr;
                uint32_t addr = Bhi + row * 128 +
                                ((uint32_t)((k16 * 2 + lc) ^ (row & 7)) << 4);
                LDSM4(bf[ni], addr);
            }
            #pragma unroll
            for (int mi = 0; mi < 2; mi++)
                #pragma unroll
                for (int ni = 0; ni < 4; ni++) {
                    MMA16816(acc[mi][2 * ni + 0], af[0][mi], bf[ni][0], bf[ni][2]);
                    MMA16816(acc[mi][2 * ni + 1], af[0][mi], bf[ni][1], bf[ni][3]);
                    MMA16816(acc[mi][2 * ni + 0], af[1][mi], bf[ni][0], bf[ni][2]);
                    MMA16816(acc[mi][2 * ni + 1], af[1][mi], bf[ni][1], bf[ni][3]);
                }
            #pragma unroll
            for (int ni = 0; ni < 4; ni++) {
                int row = nwarp * 64 + ni * 16 + lr;
                uint32_t addr = Bhi + 32768 + row * 128 +
                                ((uint32_t)((k16 * 2 + lc) ^ (row & 7)) << 4);
                LDSM4(bf[ni], addr);
            }
            #pragma unroll
            for (int mi = 0; mi < 2; mi++)
                #pragma unroll
                for (int ni = 0; ni < 4; ni++) {
                    MMA16816(acc[mi][2 * ni + 0], af[0][mi], bf[ni][0], bf[ni][2]);
                    MMA16816(acc[mi][2 * ni + 1], af[0][mi], bf[ni][1], bf[ni][3]);
                }
        }
        __syncthreads();
    }

    // ---- epilogue: scatter acc to out[b][cout][h*56+w] ----
    const int gr = lid >> 2, c2 = (lid & 3) * 2;
    float* outb = out + (size_t)b * COUT * HWSZ;
    #pragma unroll
    for (int mi = 0; mi < 2; mi++) {
        int qa = q0 + mwarp * 32 + mi * 16 + gr;
        int qb = qa + 8;
        int ha = qa / PADW - 1, wa = qa % PADW - 1;
        int hb = qb / PADW - 1, wb = qb % PADW - 1;
        bool va = ((unsigned)ha < HH) && ((unsigned)wa < WW);
        bool vb = ((unsigned)hb < HH) && ((unsigned)wb < WW);
        int pa = ha * WW + wa, pb = hb * WW + wb;
        #pragma unroll
        for (int ni = 0; ni < 8; ni++) {
            int n = nwarp * 64 + ni * 8 + c2;
            float* p = outb + (size_t)n * HWSZ;
            if (va) { p[pa] = acc[mi][ni][0]; p[HWSZ + pa] = acc[mi][ni][1]; }
            if (vb) { p[pb] = acc[mi][ni][2]; p[HWSZ + pb] = acc[mi][ni][3]; }
        }
    }
}

// ---------------------------------------------------------------------------
extern "C" void kernel_launch(void* const* d_in, const int* in_sizes, int n_in,
                              void* d_out, int out_size) {
    const float* x      = (const float*)d_in[0];  // (32,256,56,56)
    const float* att_w  = (const float*)d_in[1];  // (4,256)
    const float* weight = (const float*)d_in[2];  // (4,256,256,3,3)
    float* out = (float*)d_out;                   // (32,256,56,56)

    cudaFuncSetAttribute(conv_mma, cudaFuncAttributeMaxDynamicSharedMemorySize,
                         SMEM_BYTES_MMA);

    mean_kernel<<<BATCH * CIN, 256>>>(x);
    att_kernel<<<1, 128>>>(att_w);
    wprep_kernel<<<dim3(COUT, BATCH), 256>>>(weight);
    transpose_kernel<<<dim3(98, 4, BATCH), 256>>>(x);
    conv_mma<<<dim3(MTILES, BATCH), 512, SMEM_BYTES_MMA>>>(out);
}

// round 6
// speedup vs baseline: 3.7244x; 1.3422x over previous
#include <cuda_runtime.h>
#include <cuda_fp16.h>
#include <math.h>
#include <stdint.h>

#define BATCH 32
#define CIN   256
#define COUT  256
#define NEXP  4
#define HH    56
#define WW    56
#define HWSZ  3136

#define PADW    58
#define QCNT    3364           // 58*58 padded positions
#define GUARD   64
#define ROWSPAD 3712           // GUARD + 28*128 + GUARD
#define MTILES  27             // ceil(3364/128)

// ---------------------------------------------------------------------------
// Scratch (__device__ globals zero-initialized; guard/border rows stay 0)
// ---------------------------------------------------------------------------
__device__ float g_pooled[BATCH * CIN];
__device__ float g_att[BATCH * NEXP];
__device__ __half g_xt_hi[(size_t)BATCH * ROWSPAD * CIN];
__device__ __half g_xt_lo[(size_t)BATCH * ROWSPAD * CIN];
__device__ __half g_wf[(size_t)BATCH * 9 * COUT * CIN];

// ---------------------------------------------------------------------------
// PTX helpers (compute_80-era: valid on compute_103 base target)
// ---------------------------------------------------------------------------
__device__ __forceinline__ uint32_t smem_u32(const void* p) {
    uint32_t a;
    asm("{ .reg .u64 t; cvta.to.shared.u64 t, %1; cvt.u32.u64 %0, t; }"
        : "=r"(a) : "l"(p));
    return a;
}
#define CP_ASYNC16(dst, src) \
    asm volatile("cp.async.cg.shared.global [%0], [%1], 16;" \
                 :: "r"(dst), "l"(src) : "memory")
#define CP_COMMIT() asm volatile("cp.async.commit_group;" ::: "memory")
#define CP_WAIT0()  asm volatile("cp.async.wait_group 0;" ::: "memory")
#define CP_WAIT1()  asm volatile("cp.async.wait_group 1;" ::: "memory")

#define LDSM4(r, addr) \
    asm volatile("ldmatrix.sync.aligned.m8n8.x4.shared.b16 {%0,%1,%2,%3}, [%4];" \
                 : "=r"((r)[0]), "=r"((r)[1]), "=r"((r)[2]), "=r"((r)[3]) \
                 : "r"(addr))

#define MMA16816(d, a, b0, b1) \
    asm volatile("mma.sync.aligned.m16n8k16.row.col.f32.f16.f16.f32 " \
                 "{%0,%1,%2,%3}, {%4,%5,%6,%7}, {%8,%9}, {%0,%1,%2,%3};" \
                 : "+f"((d)[0]), "+f"((d)[1]), "+f"((d)[2]), "+f"((d)[3]) \
                 : "r"((a)[0]), "r"((a)[1]), "r"((a)[2]), "r"((a)[3]), \
                   "r"(b0), "r"(b1))

// ---------------------------------------------------------------------------
// Kernel 1: per-(b,c) spatial mean
// ---------------------------------------------------------------------------
__global__ void mean_kernel(const float* __restrict__ x) {
    int bc = blockIdx.x;
    const float4* p = reinterpret_cast<const float4*>(x + (size_t)bc * HWSZ);
    float s = 0.f;
    for (int i = threadIdx.x; i < HWSZ / 4; i += 256) {
        float4 v = p[i];
        s += (v.x + v.y) + (v.z + v.w);
    }
    #pragma unroll
    for (int o = 16; o; o >>= 1) s += __shfl_xor_sync(0xffffffffu, s, o);
    __shared__ float ws[8];
    if ((threadIdx.x & 31) == 0) ws[threadIdx.x >> 5] = s;
    __syncthreads();
    if (threadIdx.x == 0) {
        float t = 0.f;
        #pragma unroll
        for (int i = 0; i < 8; i++) t += ws[i];
        g_pooled[bc] = t * (1.0f / (float)HWSZ);
    }
}

// ---------------------------------------------------------------------------
// Kernel 2: att = sigmoid(pooled @ att_w^T)
// ---------------------------------------------------------------------------
__global__ void att_kernel(const float* __restrict__ att_w) {
    int idx = threadIdx.x;
    int b = idx >> 2, k = idx & 3;
    const float* pr = g_pooled + b * CIN;
    const float* wr = att_w + k * CIN;
    float s = 0.f;
    #pragma unroll 8
    for (int c = 0; c < CIN; c++) s += pr[c] * wr[c];
    g_att[idx] = 1.0f / (1.0f + expf(-s));
}

// ---------------------------------------------------------------------------
// Kernel 3: aggregate weights -> fp16, layout [b][t][cout][ci]
// ---------------------------------------------------------------------------
__global__ void wprep_kernel(const float* __restrict__ weight) {
    int o = blockIdx.x, b = blockIdx.y, ci = threadIdx.x;
    float a[NEXP];
    #pragma unroll
    for (int k = 0; k < NEXP; k++) a[k] = g_att[b * NEXP + k];
    #pragma unroll
    for (int t = 0; t < 9; t++) {
        float v = 0.f;
        #pragma unroll
        for (int k = 0; k < NEXP; k++)
            v += a[k] * weight[(((size_t)k * COUT + o) * CIN + ci) * 9 + t];
        size_t p = (((size_t)b * 9 + t) * COUT + o) * CIN + ci;
        g_wf[p] = __float2half_rn(v);
    }
}

// ---------------------------------------------------------------------------
// Kernel 4: transpose x -> padded position-major fp16 hi/lo split
// ---------------------------------------------------------------------------
__global__ void __launch_bounds__(256) transpose_kernel(const float* __restrict__ x) {
    __shared__ float tile[64][33];
    int b   = blockIdx.z;
    int ci0 = blockIdx.y * 64;
    int p0  = blockIdx.x * 32;
    int tid = threadIdx.x;
    int px = tid & 31, cir = tid >> 5;
    #pragma unroll
    for (int i = 0; i < 8; i++) {
        int ci = cir * 8 + i;
        tile[ci][px] = x[((size_t)b * CIN + ci0 + ci) * HWSZ + p0 + px];
    }
    __syncthreads();
    int cc = tid & 7, r = tid >> 3;
    int p = p0 + r;
    int h = p / WW, w = p % WW;
    size_t row = (size_t)b * ROWSPAD + GUARD + (size_t)(h + 1) * PADW + (w + 1);
    __align__(16) __half hi8[8];
    __align__(16) __half lo8[8];
    #pragma unroll
    for (int j = 0; j < 8; j++) {
        float v = tile[cc * 8 + j][r];
        __half hv = __float2half_rn(v);
        hi8[j] = hv;
        lo8[j] = __float2half_rn(v - __half2float(hv));
    }
    *reinterpret_cast<uint4*>(g_xt_hi + row * CIN + ci0 + cc * 8) =
        *reinterpret_cast<const uint4*>(hi8);
    *reinterpret_cast<uint4*>(g_xt_lo + row * CIN + ci0 + cc * 8) =
        *reinterpret_cast<const uint4*>(lo8);
}

// ---------------------------------------------------------------------------
// Kernel 5: implicit-GEMM conv, mma.sync fp16 2-combo split (Xhi,Xlo vs W).
// CTA tile: M=128 positions x N=256 couts, 512 threads (16 warps = 4M x 4N).
// A (x) staged once per ci-chunk as a 256-row halo (both splits); all 9 taps
// are row offsets into the resident halo. B (w, single fp16) double-buffered.
// SMEM: A 2x32KB | B 2x32KB = 128KB.
// ---------------------------------------------------------------------------
#define A_BYTES   65536
#define B_STG     32768
#define SMEM_BYTES_MMA (A_BYTES + 2 * B_STG)
#define SWZ_RC(r, c) ((uint32_t)((r) * 128 + (((c) ^ ((r) & 7)) << 4)))

__global__ void __launch_bounds__(512, 1) conv_mma(float* __restrict__ out) {
    extern __shared__ char smem[];
    const uint32_t sbase = smem_u32(smem);
    const int tid = threadIdx.x, wid = tid >> 5, lid = tid & 31;
    const int b  = blockIdx.y;
    const int q0 = blockIdx.x * 128;
    const int mwarp = wid >> 2, nwarp = wid & 3;

    const __half* xsrc[2] = {g_xt_hi + (size_t)b * ROWSPAD * CIN,
                             g_xt_lo + (size_t)b * ROWSPAD * CIN};
    const __half* wsrc    = g_wf + (size_t)b * 9 * COUT * CIN;

    float acc[2][8][4];
    #pragma unroll
    for (int mi = 0; mi < 2; mi++)
        #pragma unroll
        for (int ni = 0; ni < 8; ni++)
            #pragma unroll
            for (int e = 0; e < 4; e++) acc[mi][ni][e] = 0.f;

    // ---- A halo: 2 splits x 256 rows x 64 ci ----
    auto issueA = [&](int c4) {
        const int ci0 = c4 << 6;
        #pragma unroll
        for (int i = 0; i < 8; i++) {
            int j = tid + i * 512;
            int sp = j >> 11, r = (j >> 3) & 255, c = j & 7;
            const __half* src = xsrc[sp] + (size_t)(q0 + r) * CIN + ci0 + c * 8;
            CP_ASYNC16(sbase + sp * 32768 + SWZ_RC(r, c), src);
        }
        CP_COMMIT();
    };
    // ---- B stage: 256 n x 64 ci for (chunk, tap); s = c4*9 + t ----
    auto issueB = [&](int s) {
        const int c4 = s / 9, t = s - c4 * 9;
        const int ci0 = c4 << 6;
        const uint32_t stg = sbase + A_BYTES + (uint32_t)(s & 1) * B_STG;
        #pragma unroll
        for (int i = 0; i < 4; i++) {
            int j = tid + i * 512;
            int r = j >> 3, c = j & 7;
            const __half* src = wsrc + ((size_t)t * COUT + r) * CIN + ci0 + c * 8;
            CP_ASYNC16(stg + SWZ_RC(r, c), src);
        }
        CP_COMMIT();
    };

    issueA(0);
    issueB(0);

    const int lr = lid & 15, lc = lid >> 4;

    for (int s = 0; s < 36; s++) {
        const int c4 = s / 9, t = s - c4 * 9;
        if (t == 0 && s > 0) issueA(c4);          // prev chunk compute done
        if (s + 1 < 36) { issueB(s + 1); CP_WAIT1(); }
        else            { CP_WAIT0(); }
        __syncthreads();

        const int off = (t / 3 - 1) * PADW + (t % 3 - 1);
        const int arow0 = 64 + off + mwarp * 32;  // row in halo
        const uint32_t Bbuf = sbase + A_BYTES + (uint32_t)(s & 1) * B_STG;

        #pragma unroll
        for (int k16 = 0; k16 < 4; k16++) {
            uint32_t af[2][2][4];
            #pragma unroll
            for (int sp = 0; sp < 2; sp++)
                #pragma unroll
                for (int mi = 0; mi < 2; mi++) {
                    int row = arow0 + mi * 16 + lr;
                    uint32_t addr = sbase + sp * 32768 + row * 128 +
                                    ((uint32_t)((k16 * 2 + lc) ^ (row & 7)) << 4);
                    LDSM4(af[sp][mi], addr);
                }
            uint32_t bf[4][4];
            #pragma unroll
            for (int ni = 0; ni < 4; ni++) {
                int row = nwarp * 64 + ni * 16 + lr;
                uint32_t addr = Bbuf + row * 128 +
                                ((uint32_t)((k16 * 2 + lc) ^ (row & 7)) << 4);
                LDSM4(bf[ni], addr);
            }
            #pragma unroll
            for (int mi = 0; mi < 2; mi++)
                #pragma unroll
                for (int ni = 0; ni < 4; ni++) {
                    MMA16816(acc[mi][2 * ni + 0], af[0][mi], bf[ni][0], bf[ni][2]);
                    MMA16816(acc[mi][2 * ni + 1], af[0][mi], bf[ni][1], bf[ni][3]);
                    MMA16816(acc[mi][2 * ni + 0], af[1][mi], bf[ni][0], bf[ni][2]);
                    MMA16816(acc[mi][2 * ni + 1], af[1][mi], bf[ni][1], bf[ni][3]);
                }
        }
        __syncthreads();
    }

    // ---- epilogue: scatter acc to out[b][cout][h*56+w] ----
    const int gr = lid >> 2, c2 = (lid & 3) * 2;
    float* outb = out + (size_t)b * COUT * HWSZ;
    #pragma unroll
    for (int mi = 0; mi < 2; mi++) {
        int qa = q0 + mwarp * 32 + mi * 16 + gr;
        int qb = qa + 8;
        int ha = qa / PADW - 1, wa = qa % PADW - 1;
        int hb = qb / PADW - 1, wb = qb % PADW - 1;
        bool va = ((unsigned)ha < HH) && ((unsigned)wa < WW);
        bool vb = ((unsigned)hb < HH) && ((unsigned)wb < WW);
        int pa = ha * WW + wa, pb = hb * WW + wb;
        #pragma unroll
        for (int ni = 0; ni < 8; ni++) {
            int n = nwarp * 64 + ni * 8 + c2;
            float* p = outb + (size_t)n * HWSZ;
            if (va) { p[pa] = acc[mi][ni][0]; p[HWSZ + pa] = acc[mi][ni][1]; }
            if (vb) { p[pb] = acc[mi][ni][2]; p[HWSZ + pb] = acc[mi][ni][3]; }
        }
    }
}

// ---------------------------------------------------------------------------
extern "C" void kernel_launch(void* const* d_in, const int* in_sizes, int n_in,
                              void* d_out, int out_size) {
    const float* x      = (const float*)d_in[0];  // (32,256,56,56)
    const float* att_w  = (const float*)d_in[1];  // (4,256)
    const float* weight = (const float*)d_in[2];  // (4,256,256,3,3)
    float* out = (float*)d_out;                   // (32,256,56,56)

    cudaFuncSetAttribute(conv_mma, cudaFuncAttributeMaxDynamicSharedMemorySize,
                         SMEM_BYTES_MMA);

    mean_kernel<<<BATCH * CIN, 256>>>(x);
    att_kernel<<<1, 128>>>(att_w);
    wprep_kernel<<<dim3(COUT, BATCH), 256>>>(weight);
    transpose_kernel<<<dim3(98, 4, BATCH), 256>>>(x);
    conv_mma<<<dim3(MTILES, BATCH), 512, SMEM_BYTES_MMA>>>(out);
}